// round 14
// baseline (speedup 1.0000x reference)
#include <cuda_runtime.h>
#include <cuda_fp16.h>

// ---------------------------------------------------------------------------
// Round 14: R13 core unchanged (BK=64, single-fp16 1-term GEMMs, 256 thr,
// 2x4 warps, 64x32 warp tiles, 2-stage cp.async, 2 CTAs/SM) + kv K-split x2:
// kv grid 128 -> 256 CTAs (0.43 -> 0.86 waves), fp32 partials + merge.
// t' = m*1024 + w token permutation. rel_err ~2.1e-4 expected.
// ---------------------------------------------------------------------------

typedef unsigned int u32;

// ---------------- device buffers (single fp16) ------------------------------
__device__ __half g_X [2L * 16384 * 256];
__device__ __half g_VT[2L * 256 * 16384];
__device__ __half g_WkT[256 * 256], g_WqT[256 * 256];
__device__ __half g_PK[2L * 256 * 16384];
__device__ __half g_PQ[2L * 1024 * 256];
__device__ __half g_KV[2L * 4096 * 256];
__device__ float  g_KVp[2L * 2 * 4096 * 256];   // 2 K-slices, fp32 partials

// ---------------- smem geometry -------------------------------------------
#define TILE_B    16384                // 128 rows * 128B
#define STAGE_B   (2 * TILE_B)         // A, B
#define SM_PS     67712                // scratch after Cs (128*132*4=67584)
#define SMEM_BYTES (SM_PS + 1024)      // 68736 -> 2 CTAs/SM

// ---------------- PTX helpers ---------------------------------------------
__device__ __forceinline__ u32 smem_u32(const void* p) {
    u32 a;
    asm("{ .reg .u64 t; cvta.to.shared.u64 t, %1; cvt.u32.u64 %0, t; }"
        : "=r"(a) : "l"(p));
    return a;
}
__device__ __forceinline__ void cp_async16(u32 dst, const void* src) {
    asm volatile("cp.async.cg.shared.global [%0], [%1], 16;"
                 :: "r"(dst), "l"(src));
}
#define CP_COMMIT() asm volatile("cp.async.commit_group;" ::: "memory")
#define CP_WAIT(n)  asm volatile("cp.async.wait_group %0;" :: "n"(n) : "memory")

__device__ __forceinline__ void ldmx4(u32& r0, u32& r1, u32& r2, u32& r3, u32 a) {
    asm volatile("ldmatrix.sync.aligned.m8n8.x4.shared.b16 {%0,%1,%2,%3}, [%4];"
                 : "=r"(r0), "=r"(r1), "=r"(r2), "=r"(r3) : "r"(a));
}
__device__ __forceinline__ void mma_f16(float* c, const u32* a, const u32* b) {
    asm volatile(
        "mma.sync.aligned.m16n8k16.row.col.f32.f16.f16.f32 "
        "{%0,%1,%2,%3}, {%4,%5,%6,%7}, {%8,%9}, {%0,%1,%2,%3};"
        : "+f"(c[0]), "+f"(c[1]), "+f"(c[2]), "+f"(c[3])
        : "r"(a[0]), "r"(a[1]), "r"(a[2]), "r"(a[3]), "r"(b[0]), "r"(b[1]));
}

__device__ __forceinline__ float phi_act(float z) {
    return z > 0.f ? z + 2.f : __expf(z) + 1.f;
}
__device__ __forceinline__ u32 pack_h2(__half a, __half b) {
    __half2 p; p.x = a; p.y = b;
    return *(u32*)&p;
}
// swizzled in-tile byte offset for (row, chunk16 c in 0..7), 128B pitch
__device__ __forceinline__ u32 swz(u32 row, u32 c) {
    return row * 128 + ((c ^ (row & 7)) << 4);
}

#define ACC_DECL() float acc[4][4][4];                                   \
    _Pragma("unroll") for (int i = 0; i < 4; i++)                        \
    _Pragma("unroll") for (int j = 0; j < 4; j++)                        \
    _Pragma("unroll") for (int e = 0; e < 4; e++) acc[i][j][e] = 0.f;

// ---------------------------------------------------------------------------
// Single-term mainloop: acc(128x128, per-warp 64x32) += A(128xK) * B(128xK)^T.
// K = NB*64. 2-stage buffer, ONE barrier per 64-wide k-step.
// ---------------------------------------------------------------------------
__device__ __forceinline__ void run_gemm(
    char* sm, u32 smb,
    const __half* __restrict__ A, long sA,
    const __half* __restrict__ B, long sB,
    int NB, float acc[4][4][4])
{
    const int tid = threadIdx.x, wid = tid >> 5, lane = tid & 31;
    const int warp_m = (wid & 1) * 64, warp_n = (wid >> 1) * 32;

    auto issue_stage = [&](int s, int kb) {
        u32 base = smb + s * STAGE_B;
#pragma unroll
        for (int i = 0; i < 8; i++) {
            int ch = i * 256 + tid;                // 2048 chunks of 16B
            int tile = ch >> 10;
            u32 row = (ch >> 3) & 127, kc = ch & 7;
            const __half* gb = tile ? B : A;
            long st = tile ? sB : sA;
            cp_async16(base + tile * TILE_B + swz(row, kc),
                       gb + (long)row * st + (long)kb * 64 + kc * 8);
        }
        CP_COMMIT();
    };

    const u32 arow = warp_m + (lane & 15);
    const u32 ac   = lane >> 4;                    // chunk bit0
    const u32 brow = warp_n + (lane & 7) + ((lane >> 4) << 3);
    const u32 bc   = (lane >> 3) & 1;

    issue_stage(0, 0);

    for (int kb = 0; kb < NB; kb++) {
        CP_WAIT(0);
        __syncthreads();
        if (kb + 1 < NB) issue_stage((kb + 1) & 1, kb + 1);

        u32 sb = smb + (kb & 1) * STAGE_B;

#pragma unroll
        for (int kh = 0; kh < 4; kh++) {
            u32 aa[4][4], bb[4][2];
            const u32 aoff = swz(arow, ac + kh * 2);
            const u32 boff = swz(brow, bc + kh * 2);
#pragma unroll
            for (int i = 0; i < 4; i++)
                ldmx4(aa[i][0], aa[i][1], aa[i][2], aa[i][3],
                      sb + aoff + i * 2048);       // +16 rows = +2048B
#pragma unroll
            for (int j = 0; j < 2; j++)
                ldmx4(bb[2 * j][0], bb[2 * j][1], bb[2 * j + 1][0], bb[2 * j + 1][1],
                      sb + TILE_B + boff + j * 2048);
#pragma unroll
            for (int i = 0; i < 4; i++)
#pragma unroll
                for (int j = 0; j < 4; j++)
                    mma_f16(acc[i][j], aa[i], bb[j]);
        }
    }
    __syncthreads();   // protect smem before epilogue staging reuses it
}

// Store per-warp accumulators into Cs[128][132] f32 (reuses stage memory).
__device__ __forceinline__ void stage_C(char* sm, float acc[4][4][4])
{
    const int tid = threadIdx.x, wid = tid >> 5, lane = tid & 31;
    const int warp_m = (wid & 1) * 64, warp_n = (wid >> 1) * 32;
    float* Cs = (float*)sm;
#pragma unroll
    for (int i = 0; i < 4; i++)
#pragma unroll
        for (int j = 0; j < 4; j++) {
            int r = warp_m + i * 16 + (lane >> 2);
            int c = warp_n + j * 8 + (lane & 3) * 2;
            *(float2*)&Cs[r * 132 + c] =
                make_float2(acc[i][j][0], acc[i][j][1]);
            *(float2*)&Cs[(r + 8) * 132 + c] =
                make_float2(acc[i][j][2], acc[i][j][3]);
        }
    __syncthreads();
}

// ---------------------------------------------------------------------------
// proj kernel: blockIdx.x<256 -> K-projection (M=c, N=tokens),
//              else            -> Q-projection (M=r, N=c).  K=256 (NB=4).
// ---------------------------------------------------------------------------
__global__ __launch_bounds__(256) void proj_kernel(
    const float* __restrict__ bk, const float* __restrict__ bq)
{
    extern __shared__ char sm[];
    u32 smb = smem_u32(sm);
    const int tid = threadIdx.x;
    const int b = blockIdx.y;
    const bool isK = blockIdx.x < 256;
    int c0, t0 = 0, r0 = 0;
    const __half *A, *B;
    if (isK) {
        c0 = (blockIdx.x >> 7) * 128;
        t0 = (blockIdx.x & 127) * 128;
        A = g_WkT + c0 * 256;
        B = g_X + ((long)b * 16384 + t0) * 256;
    } else {
        int xi = blockIdx.x - 256;
        r0 = (xi >> 1) * 128;
        c0 = (xi & 1) * 128;
        A = g_X + ((long)b * 16384 + r0) * 256;
        B = g_WqT + c0 * 256;
    }

    ACC_DECL();
    run_gemm(sm, smb, A, 256, B, 256, 4, acc);
    stage_C(sm, acc);
    const float* Cs = (const float*)sm;

    if (isK) {
        const int w0 = t0 >> 4;   // 8 windows in this token tile
#pragma unroll
        for (int it = 0; it < 8; it++) {
            int task = it * 256 + tid;            // 2048 = 128 c x 16 m
            int c = task >> 4, m = task & 15;
            float bias = bk[c0 + c];
            u32 H[4];
#pragma unroll
            for (int wl = 0; wl < 4; wl++) {
                float x0 = phi_act(Cs[c * 132 + (2 * wl) * 16 + m] + bias);
                float x1 = phi_act(Cs[c * 132 + (2 * wl + 1) * 16 + m] + bias);
                H[wl] = pack_h2(__float2half_rn(x0), __float2half_rn(x1));
            }
            long off = ((long)b * 256 + c0 + c) * 16384 + m * 1024 + w0;
            *(uint4*)(g_PK + off) = make_uint4(H[0], H[1], H[2], H[3]);
        }
    } else {
#pragma unroll
        for (int it = 0; it < 8; it++) {
            int task = it * 256 + tid;            // 2048 = 128 r x 16 chunks
            int r = task >> 4, ch = task & 15;
            u32 H[4];
#pragma unroll
            for (int p = 0; p < 4; p++) {
                int col = ch * 8 + 2 * p;
                float x0 = phi_act(Cs[r * 132 + col] + bq[c0 + col]);
                float x1 = phi_act(Cs[r * 132 + col + 1] + bq[c0 + col + 1]);
                H[p] = pack_h2(__float2half_rn(x0), __float2half_rn(x1));
            }
            long off = ((long)b * 1024 + r0 + r) * 256 + c0 + ch * 8;
            *(uint4*)(g_PQ + off) = make_uint4(H[0], H[1], H[2], H[3]);
        }
    }
}

// ---------------------------------------------------------------------------
// kv kernel (partial): one 512-token K-slice of
// KVT[b][m*256+d][c] = sum_{t'} VT[d][t'] phiKT[c][t'].
// grid (dtile=2, ctile=2, slice*32 + b*16 + m), NB=8. fp32 partial output.
// ---------------------------------------------------------------------------
__global__ __launch_bounds__(256) void kv_kernel()
{
    extern __shared__ char sm[];
    u32 smb = smem_u32(sm);
    const int tid = threadIdx.x;
    const int zz = blockIdx.z;
    const int slice = zz >> 5, bm = zz & 31;
    const int b = bm >> 4, m = bm & 15;
    const int d0 = blockIdx.x * 128, c0 = blockIdx.y * 128;
    const long abase = ((long)b * 256 + d0) * 16384 + m * 1024 + slice * 512;
    const long bbase = ((long)b * 256 + c0) * 16384 + m * 1024 + slice * 512;

    ACC_DECL();
    run_gemm(sm, smb, g_VT + abase, 16384, g_PK + bbase, 16384, 8, acc);
    stage_C(sm, acc);
    const float* Cs = (const float*)sm;

    float* dstS = g_KVp + (long)slice * (2L * 4096 * 256);
#pragma unroll
    for (int it = 0; it < 8; it++) {
        int task = it * 256 + tid;                // 2048 = 128 d x 16 chunks
        int d = task >> 4, ch = task & 15;
        float* dst = dstS + ((long)b * 4096 + m * 256 + d0 + d) * 256 + c0 + ch * 8;
        *(float4*)(dst)     = *(const float4*)&Cs[d * 132 + ch * 8];
        *(float4*)(dst + 4) = *(const float4*)&Cs[d * 132 + ch * 8 + 4];
    }
}

// ---------------------------------------------------------------------------
// kv merge: sum 2 fp32 slices, round once to fp16. 2M elements.
// ---------------------------------------------------------------------------
__global__ __launch_bounds__(256) void kv_merge_kernel()
{
    const long S = 2L * 4096 * 256;
    long i = (long)blockIdx.x * 256 + threadIdx.x;   // float4 index
    float4 a0 = ((const float4*)g_KVp)[i];
    float4 a1 = ((const float4*)(g_KVp + S))[i];
    u32 h01 = pack_h2(__float2half_rn(a0.x + a1.x), __float2half_rn(a0.y + a1.y));
    u32 h23 = pack_h2(__float2half_rn(a0.z + a1.z), __float2half_rn(a0.w + a1.w));
    ((uint2*)g_KV)[i] = make_uint2(h01, h23);
}

// ---------------------------------------------------------------------------
// att kernel: out[b][w*256+n*16+m][d] = sum_c phiQ[r][c] KVT[m*256+d][c] + p.
// grid (rtile=8, jtile=32, b). K=256 (NB=4).
// ---------------------------------------------------------------------------
__global__ __launch_bounds__(256) void att_kernel(
    const float* __restrict__ embed, const float* __restrict__ Wp,
    const float* __restrict__ bp, float* __restrict__ out)
{
    extern __shared__ char sm[];
    u32 smb = smem_u32(sm);
    const int tid = threadIdx.x;
    const int b = blockIdx.z;
    const int r0 = blockIdx.x * 128;
    const int j0 = blockIdx.y * 128;
    const int m = j0 >> 8, d0 = j0 & 255;
    const long abase = ((long)b * 1024 + r0) * 256;
    const long bbase = ((long)b * 4096 + j0) * 256;

    if (tid < 128) {
        int r = r0 + tid, w = r >> 4, n = r & 15;
        const float* e = embed + ((((long)b * 1024 + w) * 16 + n) * 16 + m) * 3;
        ((float*)(sm + SM_PS))[tid] =
            e[0] * Wp[0] + e[1] * Wp[1] + e[2] * Wp[2] + bp[0];
    }

    ACC_DECL();
    run_gemm(sm, smb, g_PQ + abase, 256, g_KV + bbase, 256, 4, acc);
    stage_C(sm, acc);
    const float* Cs = (const float*)sm;

#pragma unroll
    for (int it = 0; it < 16; it++) {
        int task = it * 256 + tid;                // 4096 = 128 r x 32 f4-chunks
        int r = task >> 5, ch = task & 31;
        float4 v = *(const float4*)&Cs[r * 132 + ch * 4];
        float p = ((const float*)(sm + SM_PS))[r];
        v.x += p; v.y += p; v.z += p; v.w += p;
        int rg = r0 + r, w = rg >> 4, n = rg & 15;
        long t = (long)w * 256 + n * 16 + m;
        *(float4*)(out + ((long)b * 16384 + t) * 256 + d0 + ch * 4) = v;
    }
}

// ---------------------------------------------------------------------------
// Fused prep kernel (1D grid, 8320 blocks, 256 threads):
//   id < 8192 : VT transpose block (32w x 32d) + X fp16 emission.
//   id >= 8192: W transpose block (32x32 tile of Wk or Wq).
// ---------------------------------------------------------------------------
__global__ __launch_bounds__(256) void prep_fused(
    const float* __restrict__ X,
    const float* __restrict__ Wk, const float* __restrict__ Wq)
{
    __shared__ float tile[32][33];
    const int id = blockIdx.x;
    const int dx = threadIdx.x & 31, dy = threadIdx.x >> 5;

    if (id < 8192) {
        const int wt = id & 31, dt = (id >> 5) & 7, bm = id >> 8;
        const int b = bm >> 4, m = bm & 15;
        const int w0 = wt * 32, d0 = dt * 32;
#pragma unroll
        for (int p = 0; p < 4; p++) {
            int w = w0 + dy + p * 8;
            long idx = ((long)b * 16384 + (long)w * 16 + m) * 256 + d0 + dx;
            float v = X[idx];
            tile[dy + p * 8][dx] = v;
            g_X[idx] = __float2half_rn(v);
        }
        __syncthreads();
#pragma unroll
        for (int p = 0; p < 4; p++) {
            int d = d0 + dy + p * 8;
            float v = tile[dx][dy + p * 8];
            long off = ((long)b * 256 + d) * 16384 + m * 1024 + w0 + dx;
            g_VT[off] = __float2half_rn(v);
        }
    } else {
        const int iw = id - 8192;
        const int isQ = iw >> 6;
        const int k0 = ((iw >> 3) & 7) * 32, n0 = (iw & 7) * 32;
        const float* W = isQ ? Wq : Wk;
        __half* T = isQ ? g_WqT : g_WkT;
#pragma unroll
        for (int p = 0; p < 4; p++)
            tile[dy + p * 8][dx] = W[(k0 + dy + p * 8) * 256 + n0 + dx];
        __syncthreads();
#pragma unroll
        for (int p = 0; p < 4; p++) {
            float v = tile[dx][dy + p * 8];
            int off = (n0 + dy + p * 8) * 256 + k0 + dx;
            T[off] = __float2half_rn(v);
        }
    }
}

// ---------------------------------------------------------------------------
// Inputs (metadata order): input, embed_qk, Wq, bq, Wk, bk, Wp, bp
// ---------------------------------------------------------------------------
extern "C" void kernel_launch(void* const* d_in, const int* in_sizes, int n_in,
                              void* d_out, int out_size)
{
    const float* input = (const float*)d_in[0];
    const float* embed = (const float*)d_in[1];
    const float* Wq    = (const float*)d_in[2];
    const float* bq    = (const float*)d_in[3];
    const float* Wk    = (const float*)d_in[4];
    const float* bk    = (const float*)d_in[5];
    const float* Wp    = (const float*)d_in[6];
    const float* bp    = (const float*)d_in[7];
    float* out = (float*)d_out;

    cudaFuncSetAttribute(proj_kernel, cudaFuncAttributeMaxDynamicSharedMemorySize, SMEM_BYTES);
    cudaFuncSetAttribute(kv_kernel,   cudaFuncAttributeMaxDynamicSharedMemorySize, SMEM_BYTES);
    cudaFuncSetAttribute(att_kernel,  cudaFuncAttributeMaxDynamicSharedMemorySize, SMEM_BYTES);

    prep_fused<<<8320, 256>>>(input, Wk, Wq);

    proj_kernel<<<dim3(272, 2), 256, SMEM_BYTES>>>(bk, bq);
    kv_kernel<<<dim3(2, 2, 64), 256, SMEM_BYTES>>>();
    kv_merge_kernel<<<2048, 256>>>();
    att_kernel<<<dim3(8, 32, 2), 256, SMEM_BYTES>>>(embed, Wp, bp, out);
}

// round 15
// speedup vs baseline: 1.1240x; 1.1240x over previous
#include <cuda_runtime.h>
#include <cuda_fp16.h>

// ---------------------------------------------------------------------------
// Round 15: exact R13 config (82.4us best: BK=64, single-fp16 1-term GEMMs,
// plain kv NB=16) + direct-register epilogues for kv and att (skip the
// stage_C smem round-trip; output mapping is fragment-aligned there).
// proj keeps stage_C (needs the m-permutation transpose).
// Core: 256 thr, 2x4 warps, 64x32 warp tiles, 128B-pitch swizzle
// phys = row*128 + ((c ^ (row&7))<<4), 2-stage cp.async, 1 barrier/k-step,
// 2 CTAs/SM. t' = m*1024 + w. rel_err 2.1e-4 (bit-identical to R13).
// ---------------------------------------------------------------------------

typedef unsigned int u32;

// ---------------- device buffers (single fp16) ------------------------------
__device__ __half g_X [2L * 16384 * 256];
__device__ __half g_VT[2L * 256 * 16384];
__device__ __half g_WkT[256 * 256], g_WqT[256 * 256];
__device__ __half g_PK[2L * 256 * 16384];
__device__ __half g_PQ[2L * 1024 * 256];
__device__ __half g_KV[2L * 4096 * 256];

// ---------------- smem geometry -------------------------------------------
#define TILE_B    16384                // 128 rows * 128B
#define STAGE_B   (2 * TILE_B)         // A, B
#define SM_PS     67712                // scratch after Cs (128*132*4=67584)
#define SMEM_BYTES (SM_PS + 1024)      // 68736 -> 2 CTAs/SM

// ---------------- PTX helpers ---------------------------------------------
__device__ __forceinline__ u32 smem_u32(const void* p) {
    u32 a;
    asm("{ .reg .u64 t; cvta.to.shared.u64 t, %1; cvt.u32.u64 %0, t; }"
        : "=r"(a) : "l"(p));
    return a;
}
__device__ __forceinline__ void cp_async16(u32 dst, const void* src) {
    asm volatile("cp.async.cg.shared.global [%0], [%1], 16;"
                 :: "r"(dst), "l"(src));
}
#define CP_COMMIT() asm volatile("cp.async.commit_group;" ::: "memory")
#define CP_WAIT(n)  asm volatile("cp.async.wait_group %0;" :: "n"(n) : "memory")

__device__ __forceinline__ void ldmx4(u32& r0, u32& r1, u32& r2, u32& r3, u32 a) {
    asm volatile("ldmatrix.sync.aligned.m8n8.x4.shared.b16 {%0,%1,%2,%3}, [%4];"
                 : "=r"(r0), "=r"(r1), "=r"(r2), "=r"(r3) : "r"(a));
}
__device__ __forceinline__ void mma_f16(float* c, const u32* a, const u32* b) {
    asm volatile(
        "mma.sync.aligned.m16n8k16.row.col.f32.f16.f16.f32 "
        "{%0,%1,%2,%3}, {%4,%5,%6,%7}, {%8,%9}, {%0,%1,%2,%3};"
        : "+f"(c[0]), "+f"(c[1]), "+f"(c[2]), "+f"(c[3])
        : "r"(a[0]), "r"(a[1]), "r"(a[2]), "r"(a[3]), "r"(b[0]), "r"(b[1]));
}

__device__ __forceinline__ float phi_act(float z) {
    return z > 0.f ? z + 2.f : __expf(z) + 1.f;
}
__device__ __forceinline__ u32 pack_h2(__half a, __half b) {
    __half2 p; p.x = a; p.y = b;
    return *(u32*)&p;
}
// swizzled in-tile byte offset for (row, chunk16 c in 0..7), 128B pitch
__device__ __forceinline__ u32 swz(u32 row, u32 c) {
    return row * 128 + ((c ^ (row & 7)) << 4);
}

#define ACC_DECL() float acc[4][4][4];                                   \
    _Pragma("unroll") for (int i = 0; i < 4; i++)                        \
    _Pragma("unroll") for (int j = 0; j < 4; j++)                        \
    _Pragma("unroll") for (int e = 0; e < 4; e++) acc[i][j][e] = 0.f;

// ---------------------------------------------------------------------------
// Single-term mainloop: acc(128x128, per-warp 64x32) += A(128xK) * B(128xK)^T.
// K = NB*64. 2-stage buffer, ONE barrier per 64-wide k-step.
// ---------------------------------------------------------------------------
__device__ __forceinline__ void run_gemm(
    char* sm, u32 smb,
    const __half* __restrict__ A, long sA,
    const __half* __restrict__ B, long sB,
    int NB, float acc[4][4][4])
{
    const int tid = threadIdx.x, wid = tid >> 5, lane = tid & 31;
    const int warp_m = (wid & 1) * 64, warp_n = (wid >> 1) * 32;

    auto issue_stage = [&](int s, int kb) {
        u32 base = smb + s * STAGE_B;
#pragma unroll
        for (int i = 0; i < 8; i++) {
            int ch = i * 256 + tid;                // 2048 chunks of 16B
            int tile = ch >> 10;
            u32 row = (ch >> 3) & 127, kc = ch & 7;
            const __half* gb = tile ? B : A;
            long st = tile ? sB : sA;
            cp_async16(base + tile * TILE_B + swz(row, kc),
                       gb + (long)row * st + (long)kb * 64 + kc * 8);
        }
        CP_COMMIT();
    };

    const u32 arow = warp_m + (lane & 15);
    const u32 ac   = lane >> 4;                    // chunk bit0
    const u32 brow = warp_n + (lane & 7) + ((lane >> 4) << 3);
    const u32 bc   = (lane >> 3) & 1;

    issue_stage(0, 0);

    for (int kb = 0; kb < NB; kb++) {
        CP_WAIT(0);
        __syncthreads();
        if (kb + 1 < NB) issue_stage((kb + 1) & 1, kb + 1);

        u32 sb = smb + (kb & 1) * STAGE_B;

#pragma unroll
        for (int kh = 0; kh < 4; kh++) {
            u32 aa[4][4], bb[4][2];
            const u32 aoff = swz(arow, ac + kh * 2);
            const u32 boff = swz(brow, bc + kh * 2);
#pragma unroll
            for (int i = 0; i < 4; i++)
                ldmx4(aa[i][0], aa[i][1], aa[i][2], aa[i][3],
                      sb + aoff + i * 2048);       // +16 rows = +2048B
#pragma unroll
            for (int j = 0; j < 2; j++)
                ldmx4(bb[2 * j][0], bb[2 * j][1], bb[2 * j + 1][0], bb[2 * j + 1][1],
                      sb + TILE_B + boff + j * 2048);
#pragma unroll
            for (int i = 0; i < 4; i++)
#pragma unroll
                for (int j = 0; j < 4; j++)
                    mma_f16(acc[i][j], aa[i], bb[j]);
        }
    }
    __syncthreads();   // protect smem before any epilogue staging reuses it
}

// Store per-warp accumulators into Cs[128][132] f32 (reuses stage memory).
__device__ __forceinline__ void stage_C(char* sm, float acc[4][4][4])
{
    const int tid = threadIdx.x, wid = tid >> 5, lane = tid & 31;
    const int warp_m = (wid & 1) * 64, warp_n = (wid >> 1) * 32;
    float* Cs = (float*)sm;
#pragma unroll
    for (int i = 0; i < 4; i++)
#pragma unroll
        for (int j = 0; j < 4; j++) {
            int r = warp_m + i * 16 + (lane >> 2);
            int c = warp_n + j * 8 + (lane & 3) * 2;
            *(float2*)&Cs[r * 132 + c] =
                make_float2(acc[i][j][0], acc[i][j][1]);
            *(float2*)&Cs[(r + 8) * 132 + c] =
                make_float2(acc[i][j][2], acc[i][j][3]);
        }
    __syncthreads();
}

// ---------------------------------------------------------------------------
// proj kernel: blockIdx.x<256 -> K-projection (M=c, N=tokens),
//              else            -> Q-projection (M=r, N=c).  K=256 (NB=4).
// ---------------------------------------------------------------------------
__global__ __launch_bounds__(256) void proj_kernel(
    const float* __restrict__ bk, const float* __restrict__ bq)
{
    extern __shared__ char sm[];
    u32 smb = smem_u32(sm);
    const int tid = threadIdx.x;
    const int b = blockIdx.y;
    const bool isK = blockIdx.x < 256;
    int c0, t0 = 0, r0 = 0;
    const __half *A, *B;
    if (isK) {
        c0 = (blockIdx.x >> 7) * 128;
        t0 = (blockIdx.x & 127) * 128;
        A = g_WkT + c0 * 256;
        B = g_X + ((long)b * 16384 + t0) * 256;
    } else {
        int xi = blockIdx.x - 256;
        r0 = (xi >> 1) * 128;
        c0 = (xi & 1) * 128;
        A = g_X + ((long)b * 16384 + r0) * 256;
        B = g_WqT + c0 * 256;
    }

    ACC_DECL();
    run_gemm(sm, smb, A, 256, B, 256, 4, acc);
    stage_C(sm, acc);
    const float* Cs = (const float*)sm;

    if (isK) {
        const int w0 = t0 >> 4;   // 8 windows in this token tile
#pragma unroll
        for (int it = 0; it < 8; it++) {
            int task = it * 256 + tid;            // 2048 = 128 c x 16 m
            int c = task >> 4, m = task & 15;
            float bias = bk[c0 + c];
            u32 H[4];
#pragma unroll
            for (int wl = 0; wl < 4; wl++) {
                float x0 = phi_act(Cs[c * 132 + (2 * wl) * 16 + m] + bias);
                float x1 = phi_act(Cs[c * 132 + (2 * wl + 1) * 16 + m] + bias);
                H[wl] = pack_h2(__float2half_rn(x0), __float2half_rn(x1));
            }
            long off = ((long)b * 256 + c0 + c) * 16384 + m * 1024 + w0;
            *(uint4*)(g_PK + off) = make_uint4(H[0], H[1], H[2], H[3]);
        }
    } else {
#pragma unroll
        for (int it = 0; it < 8; it++) {
            int task = it * 256 + tid;            // 2048 = 128 r x 16 chunks
            int r = task >> 4, ch = task & 15;
            u32 H[4];
#pragma unroll
            for (int p = 0; p < 4; p++) {
                int col = ch * 8 + 2 * p;
                float x0 = phi_act(Cs[r * 132 + col] + bq[c0 + col]);
                float x1 = phi_act(Cs[r * 132 + col + 1] + bq[c0 + col + 1]);
                H[p] = pack_h2(__float2half_rn(x0), __float2half_rn(x1));
            }
            long off = ((long)b * 1024 + r0 + r) * 256 + c0 + ch * 8;
            *(uint4*)(g_PQ + off) = make_uint4(H[0], H[1], H[2], H[3]);
        }
    }
}

// ---------------------------------------------------------------------------
// kv kernel: KVT[b][m*256+d][c] = sum_{t'} VT[d][t'] phiKT[c][t'], K=1024.
// grid (dtile=2, ctile=2, b*16+m), NB=16. Direct-register epilogue:
// frag row -> d, frag col -> c (no smem staging).
// ---------------------------------------------------------------------------
__global__ __launch_bounds__(256) void kv_kernel()
{
    extern __shared__ char sm[];
    u32 smb = smem_u32(sm);
    const int tid = threadIdx.x, wid = tid >> 5, lane = tid & 31;
    const int bm = blockIdx.z, b = bm >> 4, m = bm & 15;
    const int d0 = blockIdx.x * 128, c0 = blockIdx.y * 128;
    const long abase = ((long)b * 256 + d0) * 16384 + m * 1024;
    const long bbase = ((long)b * 256 + c0) * 16384 + m * 1024;

    ACC_DECL();
    run_gemm(sm, smb, g_VT + abase, 16384, g_PK + bbase, 16384, 16, acc);

    const int warp_m = (wid & 1) * 64, warp_n = (wid >> 1) * 32;
    const long rowbase = (long)b * 4096 + m * 256;   // KV row index base
#pragma unroll
    for (int i = 0; i < 4; i++) {
        int d_lo = d0 + warp_m + i * 16 + (lane >> 2);
#pragma unroll
        for (int j = 0; j < 4; j++) {
            int c = c0 + warp_n + j * 8 + (lane & 3) * 2;
            *(u32*)(g_KV + (rowbase + d_lo) * 256 + c) =
                pack_h2(__float2half_rn(acc[i][j][0]), __float2half_rn(acc[i][j][1]));
            *(u32*)(g_KV + (rowbase + d_lo + 8) * 256 + c) =
                pack_h2(__float2half_rn(acc[i][j][2]), __float2half_rn(acc[i][j][3]));
        }
    }
}

// ---------------------------------------------------------------------------
// att kernel: out[b][w*256+n*16+m][d] = sum_c phiQ[r][c] KVT[m*256+d][c] + p.
// grid (rtile=8, jtile=32, b). K=256 (NB=4). Direct-register epilogue:
// frag row -> r (token), frag col -> d. p bias read from smem scratch.
// ---------------------------------------------------------------------------
__global__ __launch_bounds__(256) void att_kernel(
    const float* __restrict__ embed, const float* __restrict__ Wp,
    const float* __restrict__ bp, float* __restrict__ out)
{
    extern __shared__ char sm[];
    u32 smb = smem_u32(sm);
    const int tid = threadIdx.x, wid = tid >> 5, lane = tid & 31;
    const int b = blockIdx.z;
    const int r0 = blockIdx.x * 128;
    const int j0 = blockIdx.y * 128;
    const int m = j0 >> 8, d0 = j0 & 255;
    const long abase = ((long)b * 1024 + r0) * 256;
    const long bbase = ((long)b * 4096 + j0) * 256;

    float* ps = (float*)(sm + SM_PS);
    if (tid < 128) {
        int r = r0 + tid, w = r >> 4, n = r & 15;
        const float* e = embed + ((((long)b * 1024 + w) * 16 + n) * 16 + m) * 3;
        ps[tid] = e[0] * Wp[0] + e[1] * Wp[1] + e[2] * Wp[2] + bp[0];
    }
    // ps lives above the stage buffers (SM_PS >= 2*STAGE_B); run_gemm's
    // __syncthreads before the first compute orders this write for all warps.

    ACC_DECL();
    run_gemm(sm, smb, g_PQ + abase, 256, g_KV + bbase, 256, 4, acc);

    const int warp_m = (wid & 1) * 64, warp_n = (wid >> 1) * 32;
#pragma unroll
    for (int i = 0; i < 4; i++) {
        int rl = warp_m + i * 16 + (lane >> 2);        // local row
#pragma unroll
        for (int half = 0; half < 2; half++) {
            int rr = rl + half * 8;
            float p = ps[rr];
            int rg = r0 + rr, w = rg >> 4, n = rg & 15;
            long t = (long)w * 256 + n * 16 + m;
            float* dst = out + ((long)b * 16384 + t) * 256 + d0;
#pragma unroll
            for (int j = 0; j < 4; j++) {
                int c = warp_n + j * 8 + (lane & 3) * 2;
                *(float2*)(dst + c) =
                    make_float2(acc[i][j][2 * half] + p, acc[i][j][2 * half + 1] + p);
            }
        }
    }
}

// ---------------------------------------------------------------------------
// Fused prep kernel (1D grid, 8320 blocks, 256 threads):
//   id < 8192 : VT transpose block (32w x 32d) + X fp16 emission.
//   id >= 8192: W transpose block (32x32 tile of Wk or Wq).
// ---------------------------------------------------------------------------
__global__ __launch_bounds__(256) void prep_fused(
    const float* __restrict__ X,
    const float* __restrict__ Wk, const float* __restrict__ Wq)
{
    __shared__ float tile[32][33];
    const int id = blockIdx.x;
    const int dx = threadIdx.x & 31, dy = threadIdx.x >> 5;

    if (id < 8192) {
        const int wt = id & 31, dt = (id >> 5) & 7, bm = id >> 8;
        const int b = bm >> 4, m = bm & 15;
        const int w0 = wt * 32, d0 = dt * 32;
#pragma unroll
        for (int p = 0; p < 4; p++) {
            int w = w0 + dy + p * 8;
            long idx = ((long)b * 16384 + (long)w * 16 + m) * 256 + d0 + dx;
            float v = X[idx];
            tile[dy + p * 8][dx] = v;
            g_X[idx] = __float2half_rn(v);
        }
        __syncthreads();
#pragma unroll
        for (int p = 0; p < 4; p++) {
            int d = d0 + dy + p * 8;
            float v = tile[dx][dy + p * 8];
            long off = ((long)b * 256 + d) * 16384 + m * 1024 + w0 + dx;
            g_VT[off] = __float2half_rn(v);
        }
    } else {
        const int iw = id - 8192;
        const int isQ = iw >> 6;
        const int k0 = ((iw >> 3) & 7) * 32, n0 = (iw & 7) * 32;
        const float* W = isQ ? Wq : Wk;
        __half* T = isQ ? g_WqT : g_WkT;
#pragma unroll
        for (int p = 0; p < 4; p++)
            tile[dy + p * 8][dx] = W[(k0 + dy + p * 8) * 256 + n0 + dx];
        __syncthreads();
#pragma unroll
        for (int p = 0; p < 4; p++) {
            float v = tile[dx][dy + p * 8];
            int off = (n0 + dy + p * 8) * 256 + k0 + dx;
            T[off] = __float2half_rn(v);
        }
    }
}

// ---------------------------------------------------------------------------
// Inputs (metadata order): input, embed_qk, Wq, bq, Wk, bk, Wp, bp
// ---------------------------------------------------------------------------
extern "C" void kernel_launch(void* const* d_in, const int* in_sizes, int n_in,
                              void* d_out, int out_size)
{
    const float* input = (const float*)d_in[0];
    const float* embed = (const float*)d_in[1];
    const float* Wq    = (const float*)d_in[2];
    const float* bq    = (const float*)d_in[3];
    const float* Wk    = (const float*)d_in[4];
    const float* bk    = (const float*)d_in[5];
    const float* Wp    = (const float*)d_in[6];
    const float* bp    = (const float*)d_in[7];
    float* out = (float*)d_out;

    cudaFuncSetAttribute(proj_kernel, cudaFuncAttributeMaxDynamicSharedMemorySize, SMEM_BYTES);
    cudaFuncSetAttribute(kv_kernel,   cudaFuncAttributeMaxDynamicSharedMemorySize, SMEM_BYTES);
    cudaFuncSetAttribute(att_kernel,  cudaFuncAttributeMaxDynamicSharedMemorySize, SMEM_BYTES);

    prep_fused<<<8320, 256>>>(input, Wk, Wq);

    proj_kernel<<<dim3(272, 2), 256, SMEM_BYTES>>>(bk, bq);
    kv_kernel<<<dim3(2, 2, 32), 256, SMEM_BYTES>>>();
    att_kernel<<<dim3(8, 32, 2), 256, SMEM_BYTES>>>(embed, Wp, bp, out);
}

// round 16
// speedup vs baseline: 1.3113x; 1.1666x over previous
#include <cuda_runtime.h>
#include <cuda_fp16.h>

// ---------------------------------------------------------------------------
// Round 16: ldmatrix.trans rewrite of kv -> g_VT eliminated, PK stored plain
// (t', c) -> proj gets direct-register epilogues (stage_C deleted everywhere).
//   prep: X fp32->fp16 convert + W transpose only (~50MB traffic)
//   proj: A = X (tokens), B = W^T; K path scatters rows at t' = m*1024+w
//   kv  : A = g_X via ldmatrix.trans (d, token), B = g_PK via trans (c, token)
//   att : unchanged (PQ (r,c) x KV (j,c), direct epilogue)
// Core: 256 thr, 2x4 warps, 64x32 warp tiles, BK=64, 2-stage cp.async,
// 1 barrier/k-step, 2 CTAs/SM. rel_err 2.1e-4 (bit-identical math to R15).
// ---------------------------------------------------------------------------

typedef unsigned int u32;

// ---------------- device buffers (single fp16) ------------------------------
__device__ __half g_X [2L * 16384 * 256];        // natural (b, t, d)
__device__ __half g_WkT[256 * 256], g_WqT[256 * 256];
__device__ __half g_PK[2L * 16384 * 256];        // (b, t'=m*1024+w, c)
__device__ __half g_PQ[2L * 1024 * 256];         // (b, r, c)
__device__ __half g_KV[2L * 4096 * 256];         // (b, m*256+d, c)

// ---------------- smem geometry -------------------------------------------
#define TILE_B    16384                // 16KB per operand tile
#define STAGE_B   (2 * TILE_B)
#define SM_PS     67712                // scratch (att p values)
#define SMEM_BYTES (SM_PS + 1024)      // 68736 -> 2 CTAs/SM

// ---------------- PTX helpers ---------------------------------------------
__device__ __forceinline__ u32 smem_u32(const void* p) {
    u32 a;
    asm("{ .reg .u64 t; cvta.to.shared.u64 t, %1; cvt.u32.u64 %0, t; }"
        : "=r"(a) : "l"(p));
    return a;
}
__device__ __forceinline__ void cp_async16(u32 dst, const void* src) {
    asm volatile("cp.async.cg.shared.global [%0], [%1], 16;"
                 :: "r"(dst), "l"(src));
}
#define CP_COMMIT() asm volatile("cp.async.commit_group;" ::: "memory")
#define CP_WAIT(n)  asm volatile("cp.async.wait_group %0;" :: "n"(n) : "memory")

__device__ __forceinline__ void ldmx4(u32& r0, u32& r1, u32& r2, u32& r3, u32 a) {
    asm volatile("ldmatrix.sync.aligned.m8n8.x4.shared.b16 {%0,%1,%2,%3}, [%4];"
                 : "=r"(r0), "=r"(r1), "=r"(r2), "=r"(r3) : "r"(a));
}
__device__ __forceinline__ void ldmx4t(u32& r0, u32& r1, u32& r2, u32& r3, u32 a) {
    asm volatile("ldmatrix.sync.aligned.m8n8.x4.trans.shared.b16 {%0,%1,%2,%3}, [%4];"
                 : "=r"(r0), "=r"(r1), "=r"(r2), "=r"(r3) : "r"(a));
}
__device__ __forceinline__ void mma_f16(float* c, const u32* a, const u32* b) {
    asm volatile(
        "mma.sync.aligned.m16n8k16.row.col.f32.f16.f16.f32 "
        "{%0,%1,%2,%3}, {%4,%5,%6,%7}, {%8,%9}, {%0,%1,%2,%3};"
        : "+f"(c[0]), "+f"(c[1]), "+f"(c[2]), "+f"(c[3])
        : "r"(a[0]), "r"(a[1]), "r"(a[2]), "r"(a[3]), "r"(b[0]), "r"(b[1]));
}

__device__ __forceinline__ float phi_act(float z) {
    return z > 0.f ? z + 2.f : __expf(z) + 1.f;
}
__device__ __forceinline__ u32 pack_h2(__half a, __half b) {
    __half2 p; p.x = a; p.y = b;
    return *(u32*)&p;
}
// 128B-pitch swizzle: (row, chunk16 c in 0..7)
__device__ __forceinline__ u32 swz(u32 row, u32 c) {
    return row * 128 + ((c ^ (row & 7)) << 4);
}
// 256B-pitch swizzle: (row in 0..63, chunk16 c in 0..15)
__device__ __forceinline__ u32 swz2(u32 row, u32 c) {
    return row * 256 + ((c ^ (row & 7)) << 4);
}

#define ACC_DECL() float acc[4][4][4];                                   \
    _Pragma("unroll") for (int i = 0; i < 4; i++)                        \
    _Pragma("unroll") for (int j = 0; j < 4; j++)                        \
    _Pragma("unroll") for (int e = 0; e < 4; e++) acc[i][j][e] = 0.f;

// ---------------------------------------------------------------------------
// Non-trans mainloop (proj, att): tiles 128 rows x 128B, A row-major K-contig,
// B (n,k) K-contig. K = NB*64.
// ---------------------------------------------------------------------------
__device__ __forceinline__ void run_gemm(
    char* sm, u32 smb,
    const __half* __restrict__ A, long sA,
    const __half* __restrict__ B, long sB,
    int NB, float acc[4][4][4])
{
    const int tid = threadIdx.x, wid = tid >> 5, lane = tid & 31;
    const int warp_m = (wid & 1) * 64, warp_n = (wid >> 1) * 32;

    auto issue_stage = [&](int s, int kb) {
        u32 base = smb + s * STAGE_B;
#pragma unroll
        for (int i = 0; i < 8; i++) {
            int ch = i * 256 + tid;
            int tile = ch >> 10;
            u32 row = (ch >> 3) & 127, kc = ch & 7;
            const __half* gb = tile ? B : A;
            long st = tile ? sB : sA;
            cp_async16(base + tile * TILE_B + swz(row, kc),
                       gb + (long)row * st + (long)kb * 64 + kc * 8);
        }
        CP_COMMIT();
    };

    const u32 arow = warp_m + (lane & 15);
    const u32 ac   = lane >> 4;
    const u32 brow = warp_n + (lane & 7) + ((lane >> 4) << 3);
    const u32 bc   = (lane >> 3) & 1;

    issue_stage(0, 0);

    for (int kb = 0; kb < NB; kb++) {
        CP_WAIT(0);
        __syncthreads();
        if (kb + 1 < NB) issue_stage((kb + 1) & 1, kb + 1);

        u32 sb = smb + (kb & 1) * STAGE_B;

#pragma unroll
        for (int kh = 0; kh < 4; kh++) {
            u32 aa[4][4], bb[4][2];
            const u32 aoff = swz(arow, ac + kh * 2);
            const u32 boff = swz(brow, bc + kh * 2);
#pragma unroll
            for (int i = 0; i < 4; i++)
                ldmx4(aa[i][0], aa[i][1], aa[i][2], aa[i][3],
                      sb + aoff + i * 2048);
#pragma unroll
            for (int j = 0; j < 2; j++)
                ldmx4(bb[2 * j][0], bb[2 * j][1], bb[2 * j + 1][0], bb[2 * j + 1][1],
                      sb + TILE_B + boff + j * 2048);
#pragma unroll
            for (int i = 0; i < 4; i++)
#pragma unroll
                for (int j = 0; j < 4; j++)
                    mma_f16(acc[i][j], aa[i], bb[j]);
        }
    }
    __syncthreads();
}

// ---------------------------------------------------------------------------
// Double-trans mainloop (kv): both operands stored token-major
// (64 token rows x 128 cols = 256B rows), loaded with ldmatrix.trans.
// A logical (d rows, token K), B logical (c cols, token K). K = NB*64.
// srcA row stride = sAr fp16 (X: 4096), srcB row stride = 256 (PK).
// ---------------------------------------------------------------------------
__device__ __forceinline__ void run_gemm_tt(
    char* sm, u32 smb,
    const __half* __restrict__ A, long sAr,
    const __half* __restrict__ B, long sBr,
    int NB, float acc[4][4][4])
{
    const int tid = threadIdx.x, wid = tid >> 5, lane = tid & 31;
    const int warp_m = (wid & 1) * 64, warp_n = (wid >> 1) * 32;

    auto issue_stage = [&](int s, int kb) {
        u32 base = smb + s * STAGE_B;
#pragma unroll
        for (int i = 0; i < 8; i++) {
            int ch = i * 256 + tid;                // 2048 chunks of 16B
            int tile = ch >> 10;
            u32 row = (ch >> 4) & 63, kc = ch & 15;
            const __half* gb = tile ? B : A;
            long st = tile ? sBr : sAr;
            cp_async16(base + tile * TILE_B + swz2(row, kc),
                       gb + ((long)kb * 64 + row) * st + kc * 8);
        }
        CP_COMMIT();
    };

    // trans ldmatrix lane addressing
    const u32 arow_l = (lane & 7) + ((lane >> 4) << 3);       // token row part
    const u32 ach    = (warp_m >> 3) + ((lane >> 3) & 1);     // d chunk part
    const u32 brow_l = (lane & 7) + (((lane >> 3) & 1) << 3);
    const u32 bch    = (warp_n >> 3) + (lane >> 4);

    issue_stage(0, 0);

    for (int kb = 0; kb < NB; kb++) {
        CP_WAIT(0);
        __syncthreads();
        if (kb + 1 < NB) issue_stage((kb + 1) & 1, kb + 1);

        u32 sb = smb + (kb & 1) * STAGE_B;

#pragma unroll
        for (int kh = 0; kh < 4; kh++) {
            u32 aa[4][4], bb[4][2];
#pragma unroll
            for (int i = 0; i < 4; i++)
                ldmx4t(aa[i][0], aa[i][1], aa[i][2], aa[i][3],
                       sb + swz2(kh * 16 + arow_l, ach + i * 2));
#pragma unroll
            for (int j = 0; j < 2; j++)
                ldmx4t(bb[2 * j][0], bb[2 * j][1], bb[2 * j + 1][0], bb[2 * j + 1][1],
                       sb + TILE_B + swz2(kh * 16 + brow_l, bch + j * 2));
#pragma unroll
            for (int i = 0; i < 4; i++)
#pragma unroll
                for (int j = 0; j < 4; j++)
                    mma_f16(acc[i][j], aa[i], bb[j]);
        }
    }
    __syncthreads();
}

// ---------------------------------------------------------------------------
// proj kernel: A = X token rows, B = W^T. blockIdx.x<256 -> K path (writes
// PK with row permutation t -> t' = m*1024+w), else Q path (writes PQ).
// K=256 (NB=4). Direct-register epilogue with phi + fp16 pack.
// ---------------------------------------------------------------------------
__global__ __launch_bounds__(256) void proj_kernel(
    const float* __restrict__ bk, const float* __restrict__ bq)
{
    extern __shared__ char sm[];
    u32 smb = smem_u32(sm);
    const int tid = threadIdx.x, wid = tid >> 5, lane = tid & 31;
    const int b = blockIdx.y;
    const bool isK = blockIdx.x < 256;
    int c0, t0;
    const __half *A, *B;
    const float* bias;
    if (isK) {
        t0 = (blockIdx.x & 127) * 128;
        c0 = (blockIdx.x >> 7) * 128;
        A = g_X + ((long)b * 16384 + t0) * 256;
        B = g_WkT + c0 * 256;
        bias = bk;
    } else {
        int xi = blockIdx.x - 256;
        t0 = (xi >> 1) * 128;
        c0 = (xi & 1) * 128;
        A = g_X + ((long)b * 16384 + t0) * 256;
        B = g_WqT + c0 * 256;
        bias = bq;
    }

    ACC_DECL();
    run_gemm(sm, smb, A, 256, B, 256, 4, acc);

    const int warp_m = (wid & 1) * 64, warp_n = (wid >> 1) * 32;
    // per-thread bias values for the 8 columns it owns (4 j x 2)
    float bv[4][2];
#pragma unroll
    for (int j = 0; j < 4; j++) {
        int c = c0 + warp_n + j * 8 + (lane & 3) * 2;
        bv[j][0] = bias[c]; bv[j][1] = bias[c + 1];
    }

#pragma unroll
    for (int i = 0; i < 4; i++) {
        int rl = warp_m + i * 16 + (lane >> 2);
#pragma unroll
        for (int half = 0; half < 2; half++) {
            int rg = t0 + rl + half * 8;           // global token index
            long drow;
            if (isK) {
                int w = rg >> 4, mm = rg & 15;
                drow = (long)b * 16384 + mm * 1024 + w;   // t' position
            } else {
                drow = (long)b * 1024 + rg;
            }
            __half* dstrow = (isK ? g_PK : g_PQ) + drow * 256 + c0;
#pragma unroll
            for (int j = 0; j < 4; j++) {
                int c = warp_n + j * 8 + (lane & 3) * 2;
                float x0 = phi_act(acc[i][j][2 * half]     + bv[j][0]);
                float x1 = phi_act(acc[i][j][2 * half + 1] + bv[j][1]);
                *(u32*)(dstrow + c) =
                    pack_h2(__float2half_rn(x0), __float2half_rn(x1));
            }
        }
    }
}

// ---------------------------------------------------------------------------
// kv kernel: KV[b][m*256+d][c] = sum_w X[b][w*16+m][d] * PK[b][m*1024+w][c].
// grid (dtile=2, ctile=2, b*16+m), NB=16, double-trans mainloop.
// Direct-register epilogue: frag row -> d, frag col -> c.
// ---------------------------------------------------------------------------
__global__ __launch_bounds__(256) void kv_kernel()
{
    extern __shared__ char sm[];
    u32 smb = smem_u32(sm);
    const int tid = threadIdx.x, wid = tid >> 5, lane = tid & 31;
    const int bm = blockIdx.z, b = bm >> 4, m = bm & 15;
    const int d0 = blockIdx.x * 128, c0 = blockIdx.y * 128;
    // A: X rows t = b*16384 + w*16 + m, d slice d0..; row stride 16*256 = 4096
    const __half* A = g_X + ((long)b * 16384 + m) * 256 + d0;
    // B: PK rows t' = b*16384 + m*1024 + w, c slice c0..; row stride 256
    const __half* B = g_PK + ((long)b * 16384 + m * 1024) * 256 + c0;

    ACC_DECL();
    run_gemm_tt(sm, smb, A, 4096, B, 256, 16, acc);

    const int warp_m = (wid & 1) * 64, warp_n = (wid >> 1) * 32;
    const long rowbase = (long)b * 4096 + m * 256;
#pragma unroll
    for (int i = 0; i < 4; i++) {
        int d_lo = d0 + warp_m + i * 16 + (lane >> 2);
#pragma unroll
        for (int j = 0; j < 4; j++) {
            int c = c0 + warp_n + j * 8 + (lane & 3) * 2;
            *(u32*)(g_KV + (rowbase + d_lo) * 256 + c) =
                pack_h2(__float2half_rn(acc[i][j][0]), __float2half_rn(acc[i][j][1]));
            *(u32*)(g_KV + (rowbase + d_lo + 8) * 256 + c) =
                pack_h2(__float2half_rn(acc[i][j][2]), __float2half_rn(acc[i][j][3]));
        }
    }
}

// ---------------------------------------------------------------------------
// att kernel: out[b][w*256+n*16+m][d] = sum_c PQ[r][c] KV[m*256+d][c] + p.
// grid (rtile=8, jtile=32, b). K=256 (NB=4). Direct-register epilogue.
// ---------------------------------------------------------------------------
__global__ __launch_bounds__(256) void att_kernel(
    const float* __restrict__ embed, const float* __restrict__ Wp,
    const float* __restrict__ bp, float* __restrict__ out)
{
    extern __shared__ char sm[];
    u32 smb = smem_u32(sm);
    const int tid = threadIdx.x, wid = tid >> 5, lane = tid & 31;
    const int b = blockIdx.z;
    const int r0 = blockIdx.x * 128;
    const int j0 = blockIdx.y * 128;
    const int m = j0 >> 8, d0 = j0 & 255;
    const long abase = ((long)b * 1024 + r0) * 256;
    const long bbase = ((long)b * 4096 + j0) * 256;

    float* ps = (float*)(sm + SM_PS);
    if (tid < 128) {
        int r = r0 + tid, w = r >> 4, n = r & 15;
        const float* e = embed + ((((long)b * 1024 + w) * 16 + n) * 16 + m) * 3;
        ps[tid] = e[0] * Wp[0] + e[1] * Wp[1] + e[2] * Wp[2] + bp[0];
    }
    // ps lives above the stage buffers; run_gemm's first __syncthreads orders it.

    ACC_DECL();
    run_gemm(sm, smb, g_PQ + abase, 256, g_KV + bbase, 256, 4, acc);

    const int warp_m = (wid & 1) * 64, warp_n = (wid >> 1) * 32;
#pragma unroll
    for (int i = 0; i < 4; i++) {
        int rl = warp_m + i * 16 + (lane >> 2);
#pragma unroll
        for (int half = 0; half < 2; half++) {
            int rr = rl + half * 8;
            float p = ps[rr];
            int rg = r0 + rr, w = rg >> 4, n = rg & 15;
            long t = (long)w * 256 + n * 16 + m;
            float* dst = out + ((long)b * 16384 + t) * 256 + d0;
#pragma unroll
            for (int j = 0; j < 4; j++) {
                int c = warp_n + j * 8 + (lane & 3) * 2;
                *(float2*)(dst + c) =
                    make_float2(acc[i][j][2 * half] + p, acc[i][j][2 * half + 1] + p);
            }
        }
    }
}

// ---------------------------------------------------------------------------
// prep kernel: id < 8192 -> X fp32->fp16 elementwise (float4 granularity);
//              id >= 8192 -> W transpose (32x32 tile of Wk or Wq).
// ---------------------------------------------------------------------------
__global__ __launch_bounds__(256) void prep_fused(
    const float* __restrict__ X,
    const float* __restrict__ Wk, const float* __restrict__ Wq)
{
    const int id = blockIdx.x;
    if (id < 8192) {
        long i = (long)id * 256 + threadIdx.x;   // float4 index
        float4 v = ((const float4*)X)[i];
        u32 h01 = pack_h2(__float2half_rn(v.x), __float2half_rn(v.y));
        u32 h23 = pack_h2(__float2half_rn(v.z), __float2half_rn(v.w));
        ((uint2*)g_X)[i] = make_uint2(h01, h23);
    } else {
        __shared__ float tile[32][33];
        const int dx = threadIdx.x & 31, dy = threadIdx.x >> 5;
        const int iw = id - 8192;
        const int isQ = iw >> 6;
        const int k0 = ((iw >> 3) & 7) * 32, n0 = (iw & 7) * 32;
        const float* W = isQ ? Wq : Wk;
        __half* T = isQ ? g_WqT : g_WkT;
#pragma unroll
        for (int p = 0; p < 4; p++)
            tile[dy + p * 8][dx] = W[(k0 + dy + p * 8) * 256 + n0 + dx];
        __syncthreads();
#pragma unroll
        for (int p = 0; p < 4; p++) {
            float v = tile[dx][dy + p * 8];
            int off = (n0 + dy + p * 8) * 256 + k0 + dx;
            T[off] = __float2half_rn(v);
        }
    }
}

// ---------------------------------------------------------------------------
// Inputs (metadata order): input, embed_qk, Wq, bq, Wk, bk, Wp, bp
// ---------------------------------------------------------------------------
extern "C" void kernel_launch(void* const* d_in, const int* in_sizes, int n_in,
                              void* d_out, int out_size)
{
    const float* input = (const float*)d_in[0];
    const float* embed = (const float*)d_in[1];
    const float* Wq    = (const float*)d_in[2];
    const float* bq    = (const float*)d_in[3];
    const float* Wk    = (const float*)d_in[4];
    const float* bk    = (const float*)d_in[5];
    const float* Wp    = (const float*)d_in[6];
    const float* bp    = (const float*)d_in[7];
    float* out = (float*)d_out;

    cudaFuncSetAttribute(proj_kernel, cudaFuncAttributeMaxDynamicSharedMemorySize, SMEM_BYTES);
    cudaFuncSetAttribute(kv_kernel,   cudaFuncAttributeMaxDynamicSharedMemorySize, SMEM_BYTES);
    cudaFuncSetAttribute(att_kernel,  cudaFuncAttributeMaxDynamicSharedMemorySize, SMEM_BYTES);

    prep_fused<<<8320, 256>>>(input, Wk, Wq);

    proj_kernel<<<dim3(272, 2), 256, SMEM_BYTES>>>(bk, bq);
    kv_kernel<<<dim3(2, 2, 32), 256, SMEM_BYTES>>>();
    att_kernel<<<dim3(8, 32, 2), 256, SMEM_BYTES>>>(embed, Wp, bp, out);
}

// round 17
// speedup vs baseline: 1.3209x; 1.0074x over previous
#include <cuda_runtime.h>
#include <cuda_fp16.h>

// ---------------------------------------------------------------------------
// Round 16: ldmatrix.trans rewrite of kv -> g_VT eliminated, PK stored plain
// (t', c) -> proj gets direct-register epilogues (stage_C deleted everywhere).
//   prep: X fp32->fp16 convert + W transpose only (~50MB traffic)
//   proj: A = X (tokens), B = W^T; K path scatters rows at t' = m*1024+w
//   kv  : A = g_X via ldmatrix.trans (d, token), B = g_PK via trans (c, token)
//   att : unchanged (PQ (r,c) x KV (j,c), direct epilogue)
// Core: 256 thr, 2x4 warps, 64x32 warp tiles, BK=64, 2-stage cp.async,
// 1 barrier/k-step, 2 CTAs/SM. rel_err 2.1e-4 (bit-identical math to R15).
// ---------------------------------------------------------------------------

typedef unsigned int u32;

// ---------------- device buffers (single fp16) ------------------------------
__device__ __half g_X [2L * 16384 * 256];        // natural (b, t, d)
__device__ __half g_WkT[256 * 256], g_WqT[256 * 256];
__device__ __half g_PK[2L * 16384 * 256];        // (b, t'=m*1024+w, c)
__device__ __half g_PQ[2L * 1024 * 256];         // (b, r, c)
__device__ __half g_KV[2L * 4096 * 256];         // (b, m*256+d, c)

// ---------------- smem geometry -------------------------------------------
#define TILE_B    16384                // 16KB per operand tile
#define STAGE_B   (2 * TILE_B)
#define SM_PS     67712                // scratch (att p values)
#define SMEM_BYTES (SM_PS + 1024)      // 68736 -> 2 CTAs/SM

// ---------------- PTX helpers ---------------------------------------------
__device__ __forceinline__ u32 smem_u32(const void* p) {
    u32 a;
    asm("{ .reg .u64 t; cvta.to.shared.u64 t, %1; cvt.u32.u64 %0, t; }"
        : "=r"(a) : "l"(p));
    return a;
}
__device__ __forceinline__ void cp_async16(u32 dst, const void* src) {
    asm volatile("cp.async.cg.shared.global [%0], [%1], 16;"
                 :: "r"(dst), "l"(src));
}
#define CP_COMMIT() asm volatile("cp.async.commit_group;" ::: "memory")
#define CP_WAIT(n)  asm volatile("cp.async.wait_group %0;" :: "n"(n) : "memory")

__device__ __forceinline__ void ldmx4(u32& r0, u32& r1, u32& r2, u32& r3, u32 a) {
    asm volatile("ldmatrix.sync.aligned.m8n8.x4.shared.b16 {%0,%1,%2,%3}, [%4];"
                 : "=r"(r0), "=r"(r1), "=r"(r2), "=r"(r3) : "r"(a));
}
__device__ __forceinline__ void ldmx4t(u32& r0, u32& r1, u32& r2, u32& r3, u32 a) {
    asm volatile("ldmatrix.sync.aligned.m8n8.x4.trans.shared.b16 {%0,%1,%2,%3}, [%4];"
                 : "=r"(r0), "=r"(r1), "=r"(r2), "=r"(r3) : "r"(a));
}
__device__ __forceinline__ void mma_f16(float* c, const u32* a, const u32* b) {
    asm volatile(
        "mma.sync.aligned.m16n8k16.row.col.f32.f16.f16.f32 "
        "{%0,%1,%2,%3}, {%4,%5,%6,%7}, {%8,%9}, {%0,%1,%2,%3};"
        : "+f"(c[0]), "+f"(c[1]), "+f"(c[2]), "+f"(c[3])
        : "r"(a[0]), "r"(a[1]), "r"(a[2]), "r"(a[3]), "r"(b[0]), "r"(b[1]));
}

__device__ __forceinline__ float phi_act(float z) {
    return z > 0.f ? z + 2.f : __expf(z) + 1.f;
}
__device__ __forceinline__ u32 pack_h2(__half a, __half b) {
    __half2 p; p.x = a; p.y = b;
    return *(u32*)&p;
}
// 128B-pitch swizzle: (row, chunk16 c in 0..7)
__device__ __forceinline__ u32 swz(u32 row, u32 c) {
    return row * 128 + ((c ^ (row & 7)) << 4);
}
// 256B-pitch swizzle: (row in 0..63, chunk16 c in 0..15)
__device__ __forceinline__ u32 swz2(u32 row, u32 c) {
    return row * 256 + ((c ^ (row & 7)) << 4);
}

#define ACC_DECL() float acc[4][4][4];                                   \
    _Pragma("unroll") for (int i = 0; i < 4; i++)                        \
    _Pragma("unroll") for (int j = 0; j < 4; j++)                        \
    _Pragma("unroll") for (int e = 0; e < 4; e++) acc[i][j][e] = 0.f;

// ---------------------------------------------------------------------------
// Non-trans mainloop (proj, att): tiles 128 rows x 128B, A row-major K-contig,
// B (n,k) K-contig. K = NB*64.
// ---------------------------------------------------------------------------
__device__ __forceinline__ void run_gemm(
    char* sm, u32 smb,
    const __half* __restrict__ A, long sA,
    const __half* __restrict__ B, long sB,
    int NB, float acc[4][4][4])
{
    const int tid = threadIdx.x, wid = tid >> 5, lane = tid & 31;
    const int warp_m = (wid & 1) * 64, warp_n = (wid >> 1) * 32;

    auto issue_stage = [&](int s, int kb) {
        u32 base = smb + s * STAGE_B;
#pragma unroll
        for (int i = 0; i < 8; i++) {
            int ch = i * 256 + tid;
            int tile = ch >> 10;
            u32 row = (ch >> 3) & 127, kc = ch & 7;
            const __half* gb = tile ? B : A;
            long st = tile ? sB : sA;
            cp_async16(base + tile * TILE_B + swz(row, kc),
                       gb + (long)row * st + (long)kb * 64 + kc * 8);
        }
        CP_COMMIT();
    };

    const u32 arow = warp_m + (lane & 15);
    const u32 ac   = lane >> 4;
    const u32 brow = warp_n + (lane & 7) + ((lane >> 4) << 3);
    const u32 bc   = (lane >> 3) & 1;

    issue_stage(0, 0);

    for (int kb = 0; kb < NB; kb++) {
        CP_WAIT(0);
        __syncthreads();
        if (kb + 1 < NB) issue_stage((kb + 1) & 1, kb + 1);

        u32 sb = smb + (kb & 1) * STAGE_B;

#pragma unroll
        for (int kh = 0; kh < 4; kh++) {
            u32 aa[4][4], bb[4][2];
            const u32 aoff = swz(arow, ac + kh * 2);
            const u32 boff = swz(brow, bc + kh * 2);
#pragma unroll
            for (int i = 0; i < 4; i++)
                ldmx4(aa[i][0], aa[i][1], aa[i][2], aa[i][3],
                      sb + aoff + i * 2048);
#pragma unroll
            for (int j = 0; j < 2; j++)
                ldmx4(bb[2 * j][0], bb[2 * j][1], bb[2 * j + 1][0], bb[2 * j + 1][1],
                      sb + TILE_B + boff + j * 2048);
#pragma unroll
            for (int i = 0; i < 4; i++)
#pragma unroll
                for (int j = 0; j < 4; j++)
                    mma_f16(acc[i][j], aa[i], bb[j]);
        }
    }
    __syncthreads();
}

// ---------------------------------------------------------------------------
// Double-trans mainloop (kv): both operands stored token-major
// (64 token rows x 128 cols = 256B rows), loaded with ldmatrix.trans.
// A logical (d rows, token K), B logical (c cols, token K). K = NB*64.
// srcA row stride = sAr fp16 (X: 4096), srcB row stride = 256 (PK).
// ---------------------------------------------------------------------------
__device__ __forceinline__ void run_gemm_tt(
    char* sm, u32 smb,
    const __half* __restrict__ A, long sAr,
    const __half* __restrict__ B, long sBr,
    int NB, float acc[4][4][4])
{
    const int tid = threadIdx.x, wid = tid >> 5, lane = tid & 31;
    const int warp_m = (wid & 1) * 64, warp_n = (wid >> 1) * 32;

    auto issue_stage = [&](int s, int kb) {
        u32 base = smb + s * STAGE_B;
#pragma unroll
        for (int i = 0; i < 8; i++) {
            int ch = i * 256 + tid;                // 2048 chunks of 16B
            int tile = ch >> 10;
            u32 row = (ch >> 4) & 63, kc = ch & 15;
            const __half* gb = tile ? B : A;
            long st = tile ? sBr : sAr;
            cp_async16(base + tile * TILE_B + swz2(row, kc),
                       gb + ((long)kb * 64 + row) * st + kc * 8);
        }
        CP_COMMIT();
    };

    // trans ldmatrix lane addressing
    const u32 arow_l = (lane & 7) + ((lane >> 4) << 3);       // token row part
    const u32 ach    = (warp_m >> 3) + ((lane >> 3) & 1);     // d chunk part
    const u32 brow_l = (lane & 7) + (((lane >> 3) & 1) << 3);
    const u32 bch    = (warp_n >> 3) + (lane >> 4);

    issue_stage(0, 0);

    for (int kb = 0; kb < NB; kb++) {
        CP_WAIT(0);
        __syncthreads();
        if (kb + 1 < NB) issue_stage((kb + 1) & 1, kb + 1);

        u32 sb = smb + (kb & 1) * STAGE_B;

#pragma unroll
        for (int kh = 0; kh < 4; kh++) {
            u32 aa[4][4], bb[4][2];
#pragma unroll
            for (int i = 0; i < 4; i++)
                ldmx4t(aa[i][0], aa[i][1], aa[i][2], aa[i][3],
                       sb + swz2(kh * 16 + arow_l, ach + i * 2));
#pragma unroll
            for (int j = 0; j < 2; j++)
                ldmx4t(bb[2 * j][0], bb[2 * j][1], bb[2 * j + 1][0], bb[2 * j + 1][1],
                       sb + TILE_B + swz2(kh * 16 + brow_l, bch + j * 2));
#pragma unroll
            for (int i = 0; i < 4; i++)
#pragma unroll
                for (int j = 0; j < 4; j++)
                    mma_f16(acc[i][j], aa[i], bb[j]);
        }
    }
    __syncthreads();
}

// ---------------------------------------------------------------------------
// proj kernel: A = X token rows, B = W^T. blockIdx.x<256 -> K path (writes
// PK with row permutation t -> t' = m*1024+w), else Q path (writes PQ).
// K=256 (NB=4). Direct-register epilogue with phi + fp16 pack.
// ---------------------------------------------------------------------------
__global__ __launch_bounds__(256) void proj_kernel(
    const float* __restrict__ bk, const float* __restrict__ bq)
{
    extern __shared__ char sm[];
    u32 smb = smem_u32(sm);
    const int tid = threadIdx.x, wid = tid >> 5, lane = tid & 31;
    const int b = blockIdx.y;
    const bool isK = blockIdx.x < 256;
    int c0, t0;
    const __half *A, *B;
    const float* bias;
    if (isK) {
        t0 = (blockIdx.x & 127) * 128;
        c0 = (blockIdx.x >> 7) * 128;
        A = g_X + ((long)b * 16384 + t0) * 256;
        B = g_WkT + c0 * 256;
        bias = bk;
    } else {
        int xi = blockIdx.x - 256;
        t0 = (xi >> 1) * 128;
        c0 = (xi & 1) * 128;
        A = g_X + ((long)b * 16384 + t0) * 256;
        B = g_WqT + c0 * 256;
        bias = bq;
    }

    ACC_DECL();
    run_gemm(sm, smb, A, 256, B, 256, 4, acc);

    const int warp_m = (wid & 1) * 64, warp_n = (wid >> 1) * 32;
    // per-thread bias values for the 8 columns it owns (4 j x 2)
    float bv[4][2];
#pragma unroll
    for (int j = 0; j < 4; j++) {
        int c = c0 + warp_n + j * 8 + (lane & 3) * 2;
        bv[j][0] = bias[c]; bv[j][1] = bias[c + 1];
    }

#pragma unroll
    for (int i = 0; i < 4; i++) {
        int rl = warp_m + i * 16 + (lane >> 2);
#pragma unroll
        for (int half = 0; half < 2; half++) {
            int rg = t0 + rl + half * 8;           // global token index
            long drow;
            if (isK) {
                int w = rg >> 4, mm = rg & 15;
                drow = (long)b * 16384 + mm * 1024 + w;   // t' position
            } else {
                drow = (long)b * 1024 + rg;
            }
            __half* dstrow = (isK ? g_PK : g_PQ) + drow * 256 + c0;
#pragma unroll
            for (int j = 0; j < 4; j++) {
                int c = warp_n + j * 8 + (lane & 3) * 2;
                float x0 = phi_act(acc[i][j][2 * half]     + bv[j][0]);
                float x1 = phi_act(acc[i][j][2 * half + 1] + bv[j][1]);
                *(u32*)(dstrow + c) =
                    pack_h2(__float2half_rn(x0), __float2half_rn(x1));
            }
        }
    }
}

// ---------------------------------------------------------------------------
// kv kernel: KV[b][m*256+d][c] = sum_w X[b][w*16+m][d] * PK[b][m*1024+w][c].
// grid (dtile=2, ctile=2, b*16+m), NB=16, double-trans mainloop.
// Direct-register epilogue: frag row -> d, frag col -> c.
// ---------------------------------------------------------------------------
__global__ __launch_bounds__(256) void kv_kernel()
{
    extern __shared__ char sm[];
    u32 smb = smem_u32(sm);
    const int tid = threadIdx.x, wid = tid >> 5, lane = tid & 31;
    const int bm = blockIdx.z, b = bm >> 4, m = bm & 15;
    const int d0 = blockIdx.x * 128, c0 = blockIdx.y * 128;
    // A: X rows t = b*16384 + w*16 + m, d slice d0..; row stride 16*256 = 4096
    const __half* A = g_X + ((long)b * 16384 + m) * 256 + d0;
    // B: PK rows t' = b*16384 + m*1024 + w, c slice c0..; row stride 256
    const __half* B = g_PK + ((long)b * 16384 + m * 1024) * 256 + c0;

    ACC_DECL();
    run_gemm_tt(sm, smb, A, 4096, B, 256, 16, acc);

    const int warp_m = (wid & 1) * 64, warp_n = (wid >> 1) * 32;
    const long rowbase = (long)b * 4096 + m * 256;
#pragma unroll
    for (int i = 0; i < 4; i++) {
        int d_lo = d0 + warp_m + i * 16 + (lane >> 2);
#pragma unroll
        for (int j = 0; j < 4; j++) {
            int c = c0 + warp_n + j * 8 + (lane & 3) * 2;
            *(u32*)(g_KV + (rowbase + d_lo) * 256 + c) =
                pack_h2(__float2half_rn(acc[i][j][0]), __float2half_rn(acc[i][j][1]));
            *(u32*)(g_KV + (rowbase + d_lo + 8) * 256 + c) =
                pack_h2(__float2half_rn(acc[i][j][2]), __float2half_rn(acc[i][j][3]));
        }
    }
}

// ---------------------------------------------------------------------------
// att kernel: out[b][w*256+n*16+m][d] = sum_c PQ[r][c] KV[m*256+d][c] + p.
// grid (rtile=8, jtile=32, b). K=256 (NB=4). Direct-register epilogue.
// ---------------------------------------------------------------------------
__global__ __launch_bounds__(256) void att_kernel(
    const float* __restrict__ embed, const float* __restrict__ Wp,
    const float* __restrict__ bp, float* __restrict__ out)
{
    extern __shared__ char sm[];
    u32 smb = smem_u32(sm);
    const int tid = threadIdx.x, wid = tid >> 5, lane = tid & 31;
    const int b = blockIdx.z;
    const int r0 = blockIdx.x * 128;
    const int j0 = blockIdx.y * 128;
    const int m = j0 >> 8, d0 = j0 & 255;
    const long abase = ((long)b * 1024 + r0) * 256;
    const long bbase = ((long)b * 4096 + j0) * 256;

    float* ps = (float*)(sm + SM_PS);
    if (tid < 128) {
        int r = r0 + tid, w = r >> 4, n = r & 15;
        const float* e = embed + ((((long)b * 1024 + w) * 16 + n) * 16 + m) * 3;
        ps[tid] = e[0] * Wp[0] + e[1] * Wp[1] + e[2] * Wp[2] + bp[0];
    }
    // ps lives above the stage buffers; run_gemm's first __syncthreads orders it.

    ACC_DECL();
    run_gemm(sm, smb, g_PQ + abase, 256, g_KV + bbase, 256, 4, acc);

    const int warp_m = (wid & 1) * 64, warp_n = (wid >> 1) * 32;
#pragma unroll
    for (int i = 0; i < 4; i++) {
        int rl = warp_m + i * 16 + (lane >> 2);
#pragma unroll
        for (int half = 0; half < 2; half++) {
            int rr = rl + half * 8;
            float p = ps[rr];
            int rg = r0 + rr, w = rg >> 4, n = rg & 15;
            long t = (long)w * 256 + n * 16 + m;
            float* dst = out + ((long)b * 16384 + t) * 256 + d0;
#pragma unroll
            for (int j = 0; j < 4; j++) {
                int c = warp_n + j * 8 + (lane & 3) * 2;
                *(float2*)(dst + c) =
                    make_float2(acc[i][j][2 * half] + p, acc[i][j][2 * half + 1] + p);
            }
        }
    }
}

// ---------------------------------------------------------------------------
// prep kernel: id < 8192 -> X fp32->fp16 elementwise (float4 granularity);
//              id >= 8192 -> W transpose (32x32 tile of Wk or Wq).
// ---------------------------------------------------------------------------
__global__ __launch_bounds__(256) void prep_fused(
    const float* __restrict__ X,
    const float* __restrict__ Wk, const float* __restrict__ Wq)
{
    const int id = blockIdx.x;
    if (id < 8192) {
        long i = (long)id * 256 + threadIdx.x;   // float4 index
        float4 v = ((const float4*)X)[i];
        u32 h01 = pack_h2(__float2half_rn(v.x), __float2half_rn(v.y));
        u32 h23 = pack_h2(__float2half_rn(v.z), __float2half_rn(v.w));
        ((uint2*)g_X)[i] = make_uint2(h01, h23);
    } else {
        __shared__ float tile[32][33];
        const int dx = threadIdx.x & 31, dy = threadIdx.x >> 5;
        const int iw = id - 8192;
        const int isQ = iw >> 6;
        const int k0 = ((iw >> 3) & 7) * 32, n0 = (iw & 7) * 32;
        const float* W = isQ ? Wq : Wk;
        __half* T = isQ ? g_WqT : g_WkT;
#pragma unroll
        for (int p = 0; p < 4; p++)
            tile[dy + p * 8][dx] = W[(k0 + dy + p * 8) * 256 + n0 + dx];
        __syncthreads();
#pragma unroll
        for (int p = 0; p < 4; p++) {
            float v = tile[dx][dy + p * 8];
            int off = (n0 + dy + p * 8) * 256 + k0 + dx;
            T[off] = __float2half_rn(v);
        }
    }
}

// ---------------------------------------------------------------------------
// Inputs (metadata order): input, embed_qk, Wq, bq, Wk, bk, Wp, bp
// ---------------------------------------------------------------------------
extern "C" void kernel_launch(void* const* d_in, const int* in_sizes, int n_in,
                              void* d_out, int out_size)
{
    const float* input = (const float*)d_in[0];
    const float* embed = (const float*)d_in[1];
    const float* Wq    = (const float*)d_in[2];
    const float* bq    = (const float*)d_in[3];
    const float* Wk    = (const float*)d_in[4];
    const float* bk    = (const float*)d_in[5];
    const float* Wp    = (const float*)d_in[6];
    const float* bp    = (const float*)d_in[7];
    float* out = (float*)d_out;

    cudaFuncSetAttribute(proj_kernel, cudaFuncAttributeMaxDynamicSharedMemorySize, SMEM_BYTES);
    cudaFuncSetAttribute(kv_kernel,   cudaFuncAttributeMaxDynamicSharedMemorySize, SMEM_BYTES);
    cudaFuncSetAttribute(att_kernel,  cudaFuncAttributeMaxDynamicSharedMemorySize, SMEM_BYTES);

    prep_fused<<<8320, 256>>>(input, Wk, Wq);

    proj_kernel<<<dim3(272, 2), 256, SMEM_BYTES>>>(bk, bq);
    kv_kernel<<<dim3(2, 2, 32), 256, SMEM_BYTES>>>();
    att_kernel<<<dim3(8, 32, 2), 256, SMEM_BYTES>>>(embed, Wp, bp, out);
}